// round 9
// baseline (speedup 1.0000x reference)
#include <cuda_runtime.h>
#include <cuda_bf16.h>
#include <cstdint>

#define W_DIM   21504
#define NSEG    64
#define NELEM   8192
#define TILE_R  64
#define MAX_TILES 192
#define TPB     256
#define SEG_U4  5376        // uint4 fragments per segment (86016 B)
#define NITEMS  5376

// ---------------- device globals ----------------
__device__ int  d_starts[NSEG + 1];
__device__ int2 d_tiles[MAX_TILES];
__device__ int  d_ntiles;
__device__ __align__(16) uint4 d_wb[NSEG * SEG_U4];  // mma-fragment-ordered weights

// ---------------- wrappers ----------------
__device__ __forceinline__ void ldsm4(uint32_t* r, unsigned addr) {
    asm volatile("ldmatrix.sync.aligned.m8n8.x4.shared.b16 {%0,%1,%2,%3}, [%4];"
                 : "=r"(r[0]), "=r"(r[1]), "=r"(r[2]), "=r"(r[3]) : "r"(addr));
}
__device__ __forceinline__ void mma_bf16(float* c, const uint32_t* a,
                                         uint32_t b0, uint32_t b1) {
    asm volatile("mma.sync.aligned.m16n8k16.row.col.f32.bf16.bf16.f32 "
                 "{%0,%1,%2,%3}, {%4,%5,%6,%7}, {%8,%9}, {%0,%1,%2,%3};"
                 : "+f"(c[0]), "+f"(c[1]), "+f"(c[2]), "+f"(c[3])
                 : "r"(a[0]), "r"(a[1]), "r"(a[2]), "r"(a[3]), "r"(b0), "r"(b1));
}
__device__ __forceinline__ uint32_t bfpair(float a, float b) {
    __nv_bfloat162 p = __floats2bfloat162_rn(a, b);   // .x = a = low half
    return *reinterpret_cast<uint32_t*>(&p);
}
__device__ __forceinline__ void sts_v2(unsigned addr, uint32_t a, uint32_t b) {
    asm volatile("st.shared.v2.b32 [%0], {%1,%2};" :: "r"(addr), "r"(a), "r"(b));
}

// ---------------- prekernel: wconv (fragment order) + scan ----------------
__global__ void pre_kernel(const int* __restrict__ counts,
                           const float* __restrict__ w) {
    if (blockIdx.x == NSEG) {
        __shared__ int wsum[2], wtsum[2];
        const int t = threadIdx.x;
        int c = 0, nt = 0, sc = 0, st = 0;
        if (t < 64) {
            c  = counts[t];
            nt = (c + TILE_R - 1) >> 6;
            sc = c; st = nt;
            #pragma unroll
            for (int d = 1; d < 32; d <<= 1) {
                int a = __shfl_up_sync(0xffffffffu, sc, d);
                int b = __shfl_up_sync(0xffffffffu, st, d);
                if ((t & 31) >= d) { sc += a; st += b; }
            }
            if ((t & 31) == 31) { wsum[t >> 5] = sc; wtsum[t >> 5] = st; }
        }
        __syncthreads();
        if (t < 64) {
            if (t >= 32) { sc += wsum[0]; st += wtsum[0]; }
            const int startc = sc - c;
            const int startt = st - nt;
            d_starts[t] = startc;
            if (t == 63) { d_starts[NSEG] = sc; d_ntiles = st; }
            for (int k = 0; k < nt; k++)
                d_tiles[startt + k] = make_int2(startc + TILE_R * k, t);
        }
        return;
    }
    // weight convert: scale, bf16 hi/lo split, mma fragment-lane layout.
    // frag (irr, nbl, ks, lane): uint4 {hi_r0, hi_r1, lo_r0, lo_r1}
    //   element (r,h): m = ks*16 + r*8 + (lane&3)*2 + h ; o = nbl*8 + (lane>>2)
    const int g = blockIdx.x;
    const float* wg = w + (size_t)g * W_DIM;
    uint4* dst = d_wb + (size_t)g * SEG_U4;
    for (int it = threadIdx.x; it < NITEMS; it += 256) {
        int MUL, KS, WOFF, base; float coeff; int rem;
        if (it < 4096)      { MUL=128; KS=8; WOFF=0;     base=0;    coeff=0.011048543456039806f; rem=it; }
        else if (it < 5120) { MUL=64;  KS=4; WOFF=16384; base=4096; coeff=0.015625f;             rem=it-4096; }
        else                { MUL=32;  KS=2; WOFF=20480; base=5120; coeff=0.022097086912079613f; rem=it-5120; }
        const int lane = rem & 31;
        const int fr   = rem >> 5;
        const int ks   = fr % KS;
        const int nbl  = fr / KS;
        const int o    = nbl * 8 + (lane >> 2);
        const int mb   = ks * 16 + (lane & 3) * 2;
        uint32_t hi[2], lo[2];
        #pragma unroll
        for (int r = 0; r < 2; r++) {
            float v0 = coeff * wg[(size_t)(WOFF) + (mb + r * 8)     * MUL + o];
            float v1 = coeff * wg[(size_t)(WOFF) + (mb + r * 8 + 1) * MUL + o];
            __nv_bfloat16 h0 = __float2bfloat16(v0);
            __nv_bfloat16 h1 = __float2bfloat16(v1);
            hi[r] = bfpair(v0, v1);
            lo[r] = bfpair(v0 - __bfloat162float(h0), v1 - __bfloat162float(h1));
        }
        dst[base + fr * 32 + lane] = make_uint4(hi[0], hi[1], lo[0], lo[1]);
    }
}

// ---------------- main: A in smem, B fragments direct from global ----------
template <int MUL, int DIM, int IOFF4>
__device__ __forceinline__ void run_irrep_mma(const float* __restrict__ x,
                                              float* __restrict__ y,
                                              int tile, __nv_bfloat16* As) {
    constexpr int K   = MUL;
    constexpr int CH  = MUL * DIM;
    constexpr int MP  = 64 * DIM;
    constexpr int LD  = 2 * K + 8;
    constexpr int WM  = DIM;               // m16 tiles per warp (4 warps on M')
    constexpr int NBW = MUL / 16;          // n8 blocks per warp (2 warps on N)
    constexpr int KS  = MUL / 16;

    const int2 tt  = d_tiles[tile];
    const int row0 = tt.x;
    const int g    = tt.y;
    int nrows = d_starts[g + 1] - row0;
    if (nrows > TILE_R) nrows = TILE_R;

    const unsigned sbase = (unsigned)__cvta_generic_to_shared(As);

    // ---- stage A (hi|lo planes), vectorized for all DIM ----
    const float* xt = x + (size_t)row0 * CH;
    constexpr int IPR = MUL / 4;
    for (int e = threadIdx.x; e < 64 * IPR; e += TPB) {
        int r  = e / IPR;
        int m0 = (e - r * IPR) * 4;
        const float* src = xt + (size_t)r * CH + m0 * DIM;
        float f[4 * DIM];
        if (r < nrows) {
            #pragma unroll
            for (int d = 0; d < DIM; d++) {
                float4 v = *reinterpret_cast<const float4*>(src + 4 * d);
                f[4*d] = v.x; f[4*d+1] = v.y; f[4*d+2] = v.z; f[4*d+3] = v.w;
            }
        } else {
            #pragma unroll
            for (int j = 0; j < 4 * DIM; j++) f[j] = 0.f;
        }
        #pragma unroll
        for (int i = 0; i < DIM; i++) {
            float a = f[i], b = f[DIM + i], c = f[2*DIM + i], d2 = f[3*DIM + i];
            float ha = __bfloat162float(__float2bfloat16(a));
            float hb = __bfloat162float(__float2bfloat16(b));
            float hc = __bfloat162float(__float2bfloat16(c));
            float hd = __bfloat162float(__float2bfloat16(d2));
            unsigned ab = sbase + (unsigned)((r * DIM + i) * LD + m0) * 2u;
            sts_v2(ab,          bfpair(a, b),           bfpair(c, d2));
            sts_v2(ab + 2u * K, bfpair(a - ha, b - hb), bfpair(c - hc, d2 - hd));
        }
    }
    __syncthreads();

    const int l  = threadIdx.x & 31;
    const int wp = threadIdx.x >> 5;
    const int wm = wp & 3, nh = wp >> 2;

    const unsigned a_lane = ((l & 15) * LD + ((l >> 4) << 3)) * 2u;
    const uint4* wfrag = d_wb + (size_t)g * SEG_U4 + IOFF4
                       + (size_t)(nh * NBW) * KS * 32 + l;

    float acc[WM][NBW][4];
    #pragma unroll
    for (int mt = 0; mt < WM; mt++)
        #pragma unroll
        for (int nb = 0; nb < NBW; nb++)
            #pragma unroll
            for (int q = 0; q < 4; q++) acc[mt][nb][q] = 0.f;

    for (int ks = 0; ks < KS; ks++) {
        uint32_t af[WM][2][4];
        #pragma unroll
        for (int mt = 0; mt < WM; mt++) {
            unsigned ab = sbase + (unsigned)(((wm * WM + mt) * 16) * LD) * 2u
                        + (unsigned)ks * 32u + a_lane;
            ldsm4(af[mt][0], ab);           // x hi
            ldsm4(af[mt][1], ab + K * 2u);  // x lo
        }
        #pragma unroll
        for (int nb = 0; nb < NBW; nb++) {
            const uint4 bf = wfrag[(nb * KS + ks) * 32];
            #pragma unroll
            for (int mt = 0; mt < WM; mt++) {
                mma_bf16(acc[mt][nb], af[mt][0], bf.x, bf.y);  // xh*wh
                mma_bf16(acc[mt][nb], af[mt][0], bf.z, bf.w);  // xh*wl
                mma_bf16(acc[mt][nb], af[mt][1], bf.x, bf.y);  // xl*wh
            }
        }
    }

    // ---- epilogue: C[(r,i)][o] -> y[r][o*DIM + i] ----
    float* yt = y + (size_t)row0 * CH;
    #pragma unroll
    for (int mt = 0; mt < WM; mt++) {
        const int mrow0 = (wm * WM + mt) * 16 + (l >> 2);
        #pragma unroll
        for (int nb = 0; nb < NBW; nb++) {
            const int n0 = nh * (MUL / 2) + nb * 8 + (l & 3) * 2;
            #pragma unroll
            for (int rr = 0; rr < 2; rr++) {
                const int mrow = mrow0 + rr * 8;
                const int r = mrow / DIM;
                const int i = mrow - r * DIM;
                if (r < nrows) {
                    const float v0 = acc[mt][nb][rr * 2 + 0];
                    const float v1 = acc[mt][nb][rr * 2 + 1];
                    if (DIM == 1) {
                        *reinterpret_cast<float2*>(&yt[(size_t)r * CH + n0]) =
                            make_float2(v0, v1);
                    } else {
                        yt[(size_t)r * CH + n0 * DIM + i]       = v0;
                        yt[(size_t)r * CH + (n0 + 1) * DIM + i] = v1;
                    }
                }
            }
        }
    }
}

// smem (A only): max over irreps of MP*LD*2 bytes:
//   irrep0: 64*264*2=33792; irrep1: 192*136*2=52224 (max); irrep2: 320*72*2=46080
#define SMEM_BYTES 52224

__global__ __launch_bounds__(TPB, 3)
void lin_main(const float* __restrict__ x0, const float* __restrict__ x1,
              const float* __restrict__ x2, float* __restrict__ out) {
    extern __shared__ __nv_bfloat16 smem_bf[];
    const int b    = blockIdx.x;
    const int irr  = b % 3;
    const int tile = b / 3;
    if (tile >= d_ntiles) return;
    if (irr == 0) {
        run_irrep_mma<128, 1, 0>(x0, out, tile, smem_bf);
    } else if (irr == 1) {
        run_irrep_mma<64, 3, 4096>(x1, out + (size_t)NELEM * 128, tile, smem_bf);
    } else {
        run_irrep_mma<32, 5, 5120>(x2, out + (size_t)NELEM * (128 + 192), tile, smem_bf);
    }
}

extern "C" void kernel_launch(void* const* d_in, const int* in_sizes, int n_in,
                              void* d_out, int out_size) {
    const float* x0     = (const float*)d_in[0];
    const float* x1     = (const float*)d_in[1];
    const float* x2     = (const float*)d_in[2];
    const float* w      = (const float*)d_in[3];
    const int*   counts = (const int*)d_in[4];
    float*       out    = (float*)d_out;

    cudaFuncSetAttribute(lin_main, cudaFuncAttributeMaxDynamicSharedMemorySize,
                         SMEM_BYTES);
    pre_kernel<<<NSEG + 1, 256>>>(counts, w);
    lin_main<<<3 * MAX_TILES, TPB, SMEM_BYTES>>>(x0, x1, x2, out);
}